// round 1
// baseline (speedup 1.0000x reference)
#include <cuda_runtime.h>
#include <math.h>

// ---------------------------------------------------------------------------
// MetaLearner: coordinate-wise LSTM learned optimizer, 16 sequential steps.
// D=512, C=256, U=40, T=16, B=64, P=131072, 4 groups sharing weights.
// ---------------------------------------------------------------------------

#define D 512
#define C 256
#define U 40
#define T 16
#define B 64
#define P 131072
#define NZ 160              // 4*U
#define KK 45               // 5 + U
#define PREP 10.0f

#define NEGEXPP 4.5399929762484854e-05f   // exp(-10)
#define EXPP    22026.465794806718f       // exp(+10)

// ---------------- persistent state (no allocations allowed) ----------------
__device__ float g_h[(size_t)P * U];
__device__ float g_c[(size_t)P * U];
__device__ float g_p[P];
__device__ float g_f[P];
__device__ float g_i[P];
__device__ float g_grads[P];
__device__ float g_e[B * C];
__device__ float g_losspart[16];

// ---------------------------------------------------------------------------
// Kernel A: preds/e/loss-partials.  grid 16 blocks (4 batch rows each) x 256.
// e[b,c] = 2*(pred-y)/(B*C); losspart[blk] = sum of diff^2 over its 4 rows.
// ---------------------------------------------------------------------------
__global__ void __launch_bounds__(256) stepA(
    const float* __restrict__ feats_t,
    const float* __restrict__ labels_t,
    const float* __restrict__ params, int t0)
{
    __shared__ float fr[4][D];
    __shared__ float red[256];
    int tid = threadIdx.x;
    int b0 = blockIdx.x * 4;

    for (int idx = tid; idx < 4 * D; idx += 256)
        fr[idx >> 9][idx & 511] = feats_t[b0 * D + idx];
    __syncthreads();

    const float* pm = t0 ? params : g_p;
    float acc0 = 0.f, acc1 = 0.f, acc2 = 0.f, acc3 = 0.f;
#pragma unroll 8
    for (int d = 0; d < D; d++) {
        float pv = pm[d * C + tid];
        acc0 = fmaf(fr[0][d], pv, acc0);
        acc1 = fmaf(fr[1][d], pv, acc1);
        acc2 = fmaf(fr[2][d], pv, acc2);
        acc3 = fmaf(fr[3][d], pv, acc3);
    }
    float accs[4] = {acc0, acc1, acc2, acc3};
    float ss = 0.f;
#pragma unroll
    for (int r = 0; r < 4; r++) {
        float y = labels_t[(b0 + r) * C + tid];
        float diff = accs[r] - y;                 // pred - y
        g_e[(b0 + r) * C + tid] = diff * (2.0f / 16384.0f);
        ss += diff * diff;
    }
    red[tid] = ss;
    __syncthreads();
    for (int s = 128; s > 0; s >>= 1) {
        if (tid < s) red[tid] += red[tid + s];
        __syncthreads();
    }
    if (tid == 0) g_losspart[blockIdx.x] = red[0];
}

// ---------------------------------------------------------------------------
// Kernel B: grads[d,c] = sum_b f[b,d]*e[b,c].  grid 128 blocks (4 d's) x 256.
// ---------------------------------------------------------------------------
__global__ void __launch_bounds__(256) stepB(const float* __restrict__ feats_t)
{
    __shared__ float fcol[4][B];
    int tid = threadIdx.x;
    int d0 = blockIdx.x * 4;
    {
        int b = tid & 63, r = tid >> 6;   // 256 threads cover 4*64
        fcol[r][b] = feats_t[b * D + d0 + r];
    }
    __syncthreads();

    float acc0 = 0.f, acc1 = 0.f, acc2 = 0.f, acc3 = 0.f;
#pragma unroll 8
    for (int b = 0; b < B; b++) {
        float ev = g_e[b * C + tid];
        acc0 = fmaf(fcol[0][b], ev, acc0);
        acc1 = fmaf(fcol[1][b], ev, acc1);
        acc2 = fmaf(fcol[2][b], ev, acc2);
        acc3 = fmaf(fcol[3][b], ev, acc3);
    }
    g_grads[(d0 + 0) * C + tid] = acc0;
    g_grads[(d0 + 1) * C + tid] = acc1;
    g_grads[(d0 + 2) * C + tid] = acc2;
    g_grads[(d0 + 3) * C + tid] = acc3;
}

// ---------------------------------------------------------------------------
// Kernel C: the LSTM + param update. grid 256 blocks x 256 threads.
// Each block: 8 tiles of 64 coords (512 contiguous coords; group boundaries
// 16384/49152/98304 are multiples of 512 so group is uniform per block).
// Shared layout (dynamic):
//   Ws   [45][160]   weights (rows 0-4 kernel, 5-44 recurrent)
//   bias [160], Wf[41], Wi[41], scal[4]
//   xs   [45][66]    inputs per tile, column-major (k-major), padded even
//   zs   [160][65]   z exchange, padded stride 65 (conflict-free columns)
// ---------------------------------------------------------------------------
#define XS_STR 66
#define ZS_STR 65
#define SM_WS     0
#define SM_BIAS   (45 * NZ)                 // 7200
#define SM_WF     (SM_BIAS + NZ)            // 7360
#define SM_WI     (SM_WF + 41)              // 7401
#define SM_SCAL   (SM_WI + 41)              // 7442
#define SM_XS     (SM_SCAL + 4)             // 7446  (even -> 8B aligned)
#define SM_ZS     (SM_XS + KK * XS_STR)     // 7446 + 2970 = 10416
#define SM_TOTALF (SM_ZS + NZ * ZS_STR)     // 10416 + 10400 = 20816
#define SMEM_C_BYTES (SM_TOTALF * 4)        // 83264 bytes

__device__ __forceinline__ float hsig(float x)
{
    return __saturatef(fmaf(0.2f, x, 0.5f));
}

__global__ void __launch_bounds__(256) stepC(
    const float* __restrict__ kern,   // [4,5,160]
    const float* __restrict__ rkern,  // [4,40,160]
    const float* __restrict__ bias,   // [4,160]
    const float* __restrict__ Wf,     // [4,41]
    const float* __restrict__ bf,     // [4]
    const float* __restrict__ Wi,     // [4,41]
    const float* __restrict__ bi,     // [4]
    const float* __restrict__ params, // [P]
    float* __restrict__ outp,         // d_out
    int t0, int last)
{
    extern __shared__ float sm[];
    float* Ws     = sm + SM_WS;
    float* bias_s = sm + SM_BIAS;
    float* Wf_s   = sm + SM_WF;
    float* Wi_s   = sm + SM_WI;
    float* scal   = sm + SM_SCAL;
    float* xs     = sm + SM_XS;
    float* zs     = sm + SM_ZS;

    int tid = threadIdx.x;
    int base0 = blockIdx.x * 512;
    int grp = (base0 < 16384) ? 0 : (base0 < 49152) ? 1 : (base0 < 98304) ? 2 : 3;

    // load weights for this group
    for (int idx = tid; idx < KK * NZ; idx += 256) {
        int k = idx / NZ, n = idx - k * NZ;
        Ws[idx] = (k < 5) ? kern[grp * 5 * NZ + k * NZ + n]
                          : rkern[grp * U * NZ + (k - 5) * NZ + n];
    }
    if (tid < NZ) bias_s[tid] = bias[grp * NZ + tid];
    if (tid < 41) { Wf_s[tid] = Wf[grp * 41 + tid]; Wi_s[tid] = Wi[grp * 41 + tid]; }
    if (tid == 0) {
        float L = 0.f;
#pragma unroll
        for (int bb = 0; bb < 16; bb++) L += g_losspart[bb];
        L *= (1.0f / 16384.0f);
        float a = fabsf(L);
        if (a > NEGEXPP) {
            scal[0] = logf(a) / PREP;
            scal[1] = (L > 0.f) ? 1.f : ((L < 0.f) ? -1.f : 0.f);
        } else {
            scal[0] = -1.f;
            scal[1] = EXPP * L;
        }
        scal[2] = bf[grp];
        scal[3] = bi[grp];
    }
    __syncthreads();
    float l0 = scal[0], l1 = scal[1], bfv = scal[2], biv = scal[3];

    int tm = tid & 31;     // m-lane (coords 2*tm, 2*tm+1)
    int tn = tid >> 5;     // n-group (units tn*20 .. tn*20+19)
    int warp = tn, lane = tm;

    float* hbuf = xs;      // alias: [64][41] after xs is consumed

    for (int it = 0; it < 8; it++) {
        int base = base0 + it * 64;

        // ---- fill xs (k-major: xs[k*66 + m]) ----
        if (tid < 64) {
            int coord = base + tid;
            float pv = t0 ? params[coord] : g_p[coord];
            float gv = g_grads[coord];
            float a = fabsf(gv);
            float g0, g1;
            if (a > NEGEXPP) {
                g0 = logf(a) / PREP;
                g1 = (gv > 0.f) ? 1.f : ((gv < 0.f) ? -1.f : 0.f);
            } else {
                g0 = -1.f;
                g1 = EXPP * gv;
            }
            xs[0 * XS_STR + tid] = pv;
            xs[1 * XS_STR + tid] = g0;
            xs[2 * XS_STR + tid] = g1;
            xs[3 * XS_STR + tid] = l0;
            xs[4 * XS_STR + tid] = l1;
        }
        if (t0) {
            for (int idx = tid; idx < 64 * U; idx += 256) {
                int m = idx / U, u = idx - m * U;
                xs[(5 + u) * XS_STR + m] = 0.f;
            }
        } else {
            for (int idx = tid; idx < 64 * U; idx += 256) {
                int m = idx / U, u = idx - m * U;
                xs[(5 + u) * XS_STR + m] = g_h[(size_t)(base + m) * U + u];
            }
        }
        __syncthreads();

        // ---- z = x @ W + bias ----
        float acc0[20], acc1[20];
#pragma unroll
        for (int j = 0; j < 20; j++) {
            float bv = bias_s[tn * 20 + j];
            acc0[j] = bv; acc1[j] = bv;
        }
#pragma unroll 3
        for (int k = 0; k < KK; k++) {
            float2 xv = *reinterpret_cast<const float2*>(xs + k * XS_STR + 2 * tm);
            const float4* wrow = reinterpret_cast<const float4*>(Ws + k * NZ + tn * 20);
#pragma unroll
            for (int q = 0; q < 5; q++) {
                float4 w = wrow[q];
                acc0[q*4+0] = fmaf(xv.x, w.x, acc0[q*4+0]);
                acc1[q*4+0] = fmaf(xv.y, w.x, acc1[q*4+0]);
                acc0[q*4+1] = fmaf(xv.x, w.y, acc0[q*4+1]);
                acc1[q*4+1] = fmaf(xv.y, w.y, acc1[q*4+1]);
                acc0[q*4+2] = fmaf(xv.x, w.z, acc0[q*4+2]);
                acc1[q*4+2] = fmaf(xv.y, w.z, acc1[q*4+2]);
                acc0[q*4+3] = fmaf(xv.x, w.w, acc0[q*4+3]);
                acc1[q*4+3] = fmaf(xv.y, w.w, acc1[q*4+3]);
            }
        }
#pragma unroll
        for (int j = 0; j < 20; j++) {
            zs[(tn * 20 + j) * ZS_STR + 2 * tm]     = acc0[j];
            zs[(tn * 20 + j) * ZS_STR + 2 * tm + 1] = acc1[j];
        }
        __syncthreads();

        // ---- gates + cell update (coalesced over u) ----
        for (int idx = tid; idx < 64 * U; idx += 256) {
            int m = idx / U, u = idx - m * U;
            int coord = base + m;
            float zi = zs[u * ZS_STR + m];
            float zf = zs[(U + u) * ZS_STR + m];
            float zc = zs[(2 * U + u) * ZS_STR + m];
            float zo = zs[(3 * U + u) * ZS_STR + m];
            float ig = hsig(zi), fg = hsig(zf), og = hsig(zo);
            float cprev = t0 ? 0.f : g_c[(size_t)coord * U + u];
            float cn = fmaf(fg, cprev, ig * tanhf(zc));
            float hn = og * tanhf(cn);
            g_c[(size_t)coord * U + u] = cn;
            g_h[(size_t)coord * U + u] = hn;
            hbuf[m * 41 + u] = hn;    // aliases xs (safe: xs fully consumed)
        }
        __syncthreads();

        // ---- f/i dot products + param update (warp per 8 coords) ----
        for (int ci = 0; ci < 8; ci++) {
            int m = warp * 8 + ci;
            int coord = base + m;
            float hv = hbuf[m * 41 + lane];
            float pf = hv * Wf_s[lane];
            float pi = hv * Wi_s[lane];
            if (lane < 8) {
                float h2 = hbuf[m * 41 + lane + 32];
                pf = fmaf(h2, Wf_s[lane + 32], pf);
                pi = fmaf(h2, Wi_s[lane + 32], pi);
            }
#pragma unroll
            for (int off = 16; off > 0; off >>= 1) {
                pf += __shfl_xor_sync(0xffffffffu, pf, off);
                pi += __shfl_xor_sync(0xffffffffu, pi, off);
            }
            if (lane == 0) {
                float fprev = t0 ? 0.f : g_f[coord];
                float iprev = t0 ? 0.f : g_i[coord];
                float fnew = fmaxf(fmaf(fprev, Wf_s[40], pf) + bfv, 0.f);
                float inew = fmaxf(fmaf(iprev, Wi_s[40], pi) + biv, 0.f);
                float pold = t0 ? params[coord] : g_p[coord];
                float gv = g_grads[coord];
                float pnew = fnew * pold - inew * gv;
                g_f[coord] = fnew;
                g_i[coord] = inew;
                if (last) outp[coord] = pnew;
                else      g_p[coord] = pnew;
            }
        }
        __syncthreads();   // before next tile reuses xs/zs
    }
}

// ---------------------------------------------------------------------------
extern "C" void kernel_launch(void* const* d_in, const int* in_sizes, int n_in,
                              void* d_out, int out_size)
{
    const float* feats  = (const float*)d_in[0];  // [1,16,64,512]
    const float* labels = (const float*)d_in[1];  // [1,16,64,256]
    const float* params = (const float*)d_in[2];  // [1,131072]
    const float* kern   = (const float*)d_in[3];  // [4,5,160]
    const float* rkern  = (const float*)d_in[4];  // [4,40,160]
    const float* bias   = (const float*)d_in[5];  // [4,160]
    const float* Wf     = (const float*)d_in[6];  // [4,41,1]
    const float* bf     = (const float*)d_in[7];  // [4,1]
    const float* Wi     = (const float*)d_in[8];  // [4,41,1]
    const float* bi     = (const float*)d_in[9];  // [4,1]
    float* out = (float*)d_out;

    cudaFuncSetAttribute(stepC, cudaFuncAttributeMaxDynamicSharedMemorySize,
                         SMEM_C_BYTES);

    for (int t = 0; t < T; t++) {
        const float* ft = feats  + (size_t)t * B * D;
        const float* lt = labels + (size_t)t * B * C;
        int t0 = (t == 0) ? 1 : 0;
        int last = (t == T - 1) ? 1 : 0;
        stepA<<<16, 256>>>(ft, lt, params, t0);
        stepB<<<128, 256>>>(ft);
        stepC<<<256, 256, SMEM_C_BYTES>>>(kern, rkern, bias, Wf, bf, Wi, bi,
                                          params, out, t0, last);
    }
}

// round 2
// speedup vs baseline: 1.1474x; 1.1474x over previous
#include <cuda_runtime.h>
#include <math.h>

// ---------------------------------------------------------------------------
// MetaLearner: coordinate-wise LSTM learned optimizer, 16 sequential steps.
// D=512, C=256, U=40, T=16, B=64, P=131072, 4 groups sharing weights.
// ---------------------------------------------------------------------------

#define D 512
#define C 256
#define U 40
#define T 16
#define B 64
#define P 131072
#define NZ 160              // 4*U
#define KE 43               // 3 + U   (l0,l1 folded into bias)
#define PREP 10.0f

#define NEGEXPP 4.5399929762484854e-05f   // exp(-10)
#define EXPP    22026.465794806718f       // exp(+10)

// ---------------- persistent state (no allocations allowed) ----------------
// h and c stored TRANSPOSED: [U][P] for coalesced access.
__device__ float g_h[(size_t)U * P];
__device__ float g_c[(size_t)U * P];
__device__ float g_p[P];
__device__ float g_f[P];
__device__ float g_i[P];
__device__ float g_grads[P];
__device__ __align__(16) float g_e[B * C];
__device__ float g_losspart[B];

// ---------------------------------------------------------------------------
// FMA/ALU-only tanh (no MUFU). exp2 by add-magic range reduction + deg-6
// Taylor + exponent-bit scaling; reciprocal via magic seed + 3 Newton steps.
// Abs error ~1e-7.
// ---------------------------------------------------------------------------
__device__ __forceinline__ float tanh_fma(float x)
{
    float xc = fminf(fmaxf(x, -9.0f), 9.0f);
    float y  = xc * 2.8853900817779268f;          // 2*log2(e)*x
    float r  = __fadd_rn(y, 12582912.0f);         // 1.5*2^23
    int   n  = __float_as_int(r) - 0x4B400000;
    float f  = y - __fadd_rn(r, -12582912.0f);    // f in [-0.5, 0.5]
    float p  = 1.5403530393e-4f;
    p = fmaf(p, f, 1.3333558146e-3f);
    p = fmaf(p, f, 9.6181291076e-3f);
    p = fmaf(p, f, 5.5504108665e-2f);
    p = fmaf(p, f, 2.4022650696e-1f);
    p = fmaf(p, f, 6.9314718056e-1f);
    p = fmaf(p, f, 1.0f);
    float e  = __int_as_float(__float_as_int(p) + (n << 23));  // e = exp(2x)
    float d  = e + 1.0f;
    float rc = __int_as_float(0x7EF311C3 - __float_as_int(d)); // ~1/d seed
    rc = rc * fmaf(-d, rc, 2.0f);
    rc = rc * fmaf(-d, rc, 2.0f);
    rc = rc * fmaf(-d, rc, 2.0f);
    return fmaf(-2.0f, rc, 1.0f);                 // 1 - 2/(e+1)
}

__device__ __forceinline__ float hsig(float x)
{
    return __saturatef(fmaf(0.2f, x, 0.5f));
}

// packed f32x2 fma (Blackwell)
#define FMA2(acc, a, b) \
    asm("fma.rn.f32x2 %0, %1, %2, %0;" : "+l"(acc) : "l"(a), "l"(b))

__device__ __forceinline__ float2 u2f(unsigned long long v)
{
    float2 r;
    asm("mov.b64 {%0, %1}, %2;" : "=f"(r.x), "=f"(r.y) : "l"(v));
    return r;
}
__device__ __forceinline__ unsigned long long splat2(float w)
{
    unsigned int u = __float_as_uint(w);
    return (unsigned long long)u | ((unsigned long long)u << 32);
}

// ---------------------------------------------------------------------------
// Kernel A: preds/e/loss-partials. grid 64 blocks (1 batch row) x 256.
// Threads: 64 col-quads (float4) x 4-way K split. e=2*(pred-y)/(B*C).
// ---------------------------------------------------------------------------
__global__ void __launch_bounds__(256) stepA(
    const float* __restrict__ feats_t,
    const float* __restrict__ labels_t,
    const float* __restrict__ params, int t0)
{
    __shared__ float fr[D];
    __shared__ float4 sred[256];
    __shared__ float lred[64];
    int tid = threadIdx.x;
    int b = blockIdx.x;

    for (int i = tid; i < D; i += 256) fr[i] = feats_t[b * D + i];
    __syncthreads();

    const float* pm = t0 ? params : g_p;
    const float4* pm4 = (const float4*)pm;
    int c4 = tid & 63;
    int ks = tid >> 6;
    float4 acc = make_float4(0.f, 0.f, 0.f, 0.f);
    int dbeg = ks * 128;
#pragma unroll 8
    for (int d = dbeg; d < dbeg + 128; d++) {
        float fv = fr[d];
        float4 w = pm4[d * 64 + c4];
        acc.x = fmaf(fv, w.x, acc.x);
        acc.y = fmaf(fv, w.y, acc.y);
        acc.z = fmaf(fv, w.z, acc.z);
        acc.w = fmaf(fv, w.w, acc.w);
    }
    sred[tid] = acc;
    __syncthreads();

    if (tid < 64) {
        float4 a0 = sred[tid], a1 = sred[tid + 64];
        float4 a2 = sred[tid + 128], a3 = sred[tid + 192];
        float4 s = make_float4(a0.x + a1.x + a2.x + a3.x,
                               a0.y + a1.y + a2.y + a3.y,
                               a0.z + a1.z + a2.z + a3.z,
                               a0.w + a1.w + a2.w + a3.w);
        float4 y = ((const float4*)labels_t)[b * 64 + tid];
        float4 df = make_float4(s.x - y.x, s.y - y.y, s.z - y.z, s.w - y.w);
        const float kc = 2.0f / 16384.0f;
        ((float4*)g_e)[b * 64 + tid] =
            make_float4(df.x * kc, df.y * kc, df.z * kc, df.w * kc);
        lred[tid] = df.x * df.x + df.y * df.y + df.z * df.z + df.w * df.w;
    }
    __syncthreads();
    if (tid < 32) {
        float v = lred[tid] + lred[tid + 32];
#pragma unroll
        for (int off = 16; off > 0; off >>= 1)
            v += __shfl_xor_sync(0xffffffffu, v, off);
        if (tid == 0) g_losspart[b] = v;
    }
}

// ---------------------------------------------------------------------------
// Kernel B: grads[d,c] = sum_b f[b,d]*e[b,c].  grid 128 blocks (4 d's) x 256.
// ---------------------------------------------------------------------------
__global__ void __launch_bounds__(256) stepB(const float* __restrict__ feats_t)
{
    __shared__ float fcol[4][B];
    int tid = threadIdx.x;
    int d0 = blockIdx.x * 4;
    {
        int b = tid & 63, r = tid >> 6;
        fcol[r][b] = feats_t[b * D + d0 + r];
    }
    __syncthreads();

    float acc0 = 0.f, acc1 = 0.f, acc2 = 0.f, acc3 = 0.f;
#pragma unroll 16
    for (int b = 0; b < B; b++) {
        float ev = g_e[b * C + tid];
        acc0 = fmaf(fcol[0][b], ev, acc0);
        acc1 = fmaf(fcol[1][b], ev, acc1);
        acc2 = fmaf(fcol[2][b], ev, acc2);
        acc3 = fmaf(fcol[3][b], ev, acc3);
    }
    g_grads[(d0 + 0) * C + tid] = acc0;
    g_grads[(d0 + 1) * C + tid] = acc1;
    g_grads[(d0 + 2) * C + tid] = acc2;
    g_grads[(d0 + 3) * C + tid] = acc3;
}

// ---------------------------------------------------------------------------
// Kernel C: LSTM + param update. grid 256 x 256. Each block: 512 coords in
// 8 tiles of 64. Gate-aligned mapping: lane tm owns coord pair (2tm,2tm+1),
// warp tn owns u-range [tn*5, tn*5+5) for ALL FOUR gates -> gates computed
// entirely in registers (no z exchange). FFMA2 with pre-splatted weights.
//
// smem (dynamic, 16B-aligned base):
//   Ws2     [43][4][8][6] ull  splatted weights, 66048 B (chunk 48B, 16B-al.)
//   biasEff2[160] ull           bias + l0*K3 + l1*K4, splatted
//   Wf_s[41], Wi_s[41], scal[4] floats (pad to 88)
//   xs      [43][66] floats     k-major input tile (8B-aligned float2 cols)
//   hbuf    [40][65] floats     aliases xs after GEMM
// ---------------------------------------------------------------------------
#define WS2_ULL   (43 * 4 * 8 * 6)            // 8256
#define BIAS_OFF  WS2_ULL                      // ull index
#define MISC_ULL  (WS2_ULL + 160)              // 8416
#define MISC_F    88                           // Wf 41 + Wi 41 + scal 4 + pad
#define XS_STR    66
#define HB_STR    65
#define SMEM_C_BYTES (MISC_ULL * 8 + (MISC_F + KE * XS_STR) * 4)  // 79032

__global__ void __launch_bounds__(256) stepC(
    const float* __restrict__ kern,   // [4,5,160]
    const float* __restrict__ rkern,  // [4,40,160]
    const float* __restrict__ bias,   // [4,160]
    const float* __restrict__ Wf,     // [4,41]
    const float* __restrict__ bf,     // [4]
    const float* __restrict__ Wi,     // [4,41]
    const float* __restrict__ bi,     // [4]
    const float* __restrict__ params, // [P]
    float* __restrict__ outp,
    int t0, int last)
{
    extern __shared__ __align__(16) unsigned long long smU[];
    unsigned long long* Ws2 = smU;
    unsigned long long* biasEff2 = smU + BIAS_OFF;
    float* smF  = (float*)(smU + MISC_ULL);
    float* Wf_s = smF;
    float* Wi_s = smF + 41;
    float* scal = smF + 82;
    float* xs   = smF + MISC_F;
    float* hbuf = xs;                 // alias (40*65=2600 <= 43*66=2838)

    int tid = threadIdx.x;
    int base0 = blockIdx.x * 512;
    int grp = (base0 < 16384) ? 0 : (base0 < 49152) ? 1 : (base0 < 98304) ? 2 : 3;

    // ---- phase 0: scal + raw weights ----
    if (tid == 0) {
        float L = 0.f;
#pragma unroll
        for (int bb = 0; bb < B; bb++) L += g_losspart[bb];
        L *= (1.0f / 16384.0f);
        float a = fabsf(L);
        if (a > NEGEXPP) {
            scal[0] = logf(a) / PREP;
            scal[1] = (L > 0.f) ? 1.f : ((L < 0.f) ? -1.f : 0.f);
        } else {
            scal[0] = -1.f;
            scal[1] = EXPP * L;
        }
        scal[2] = bf[grp];
        scal[3] = bi[grp];
    }
    if (tid < 41) { Wf_s[tid] = Wf[grp * 41 + tid]; Wi_s[tid] = Wi[grp * 41 + tid]; }
    // splatted weights: Ws2[((k*4+g)*8+tn)*6+uu], j = g*40+tn*5+uu
    for (int idx = tid; idx < KE * NZ; idx += 256) {
        int k = idx / NZ, j = idx - k * NZ;
        int g = j / 40, r = j - g * 40;
        int tn_ = r / 5, uu = r - tn_ * 5;
        float w = (k < 3) ? kern[grp * 800 + k * NZ + j]
                          : rkern[grp * 6400 + (k - 3) * NZ + j];
        Ws2[((k * 4 + g) * 8 + tn_) * 6 + uu] = splat2(w);
    }
    __syncthreads();
    float l0 = scal[0], l1 = scal[1], bfv = scal[2], biv = scal[3];
    if (tid < NZ) {
        float bval = bias[grp * NZ + tid]
                   + l0 * kern[grp * 800 + 3 * NZ + tid]
                   + l1 * kern[grp * 800 + 4 * NZ + tid];
        biasEff2[tid] = splat2(bval);
    }
    __syncthreads();

    int tm = tid & 31;            // coord pair (2tm, 2tm+1)
    int tn = tid >> 5;            // u-range tn*5..tn*5+4
    int u0 = tn * 5;
    const unsigned long long* wthr = Ws2 + tn * 6;

    for (int it = 0; it < 8; it++) {
        int base = base0 + it * 64;

        // ---- fill xs ----
        if (tid < 64) {
            int coord = base + tid;
            float pv = t0 ? params[coord] : g_p[coord];
            float gv = g_grads[coord];
            float a = fabsf(gv);
            float g0, g1;
            if (a > NEGEXPP) {
                g0 = logf(a) / PREP;
                g1 = (gv > 0.f) ? 1.f : ((gv < 0.f) ? -1.f : 0.f);
            } else {
                g0 = -1.f;
                g1 = EXPP * gv;
            }
            xs[0 * XS_STR + tid] = pv;
            xs[1 * XS_STR + tid] = g0;
            xs[2 * XS_STR + tid] = g1;
        }
        if (t0) {
            for (int idx = tid; idx < 64 * U; idx += 256) {
                int u = idx >> 6, m = idx & 63;
                xs[(3 + u) * XS_STR + m] = 0.f;
            }
        } else {
            for (int idx = tid; idx < 64 * U; idx += 256) {
                int u = idx >> 6, m = idx & 63;
                xs[(3 + u) * XS_STR + m] = g_h[(size_t)u * P + base + m];
            }
        }
        __syncthreads();

        // ---- GEMM: z = x @ W + biasEff (FFMA2, gate-aligned) ----
        unsigned long long accp[20];
#pragma unroll
        for (int g = 0; g < 4; g++)
#pragma unroll
            for (int uu = 0; uu < 5; uu++)
                accp[g * 5 + uu] = biasEff2[g * 40 + u0 + uu];

#pragma unroll 2
        for (int k = 0; k < KE; k++) {
            unsigned long long xv =
                *(const unsigned long long*)(xs + k * XS_STR + 2 * tm);
#pragma unroll
            for (int g = 0; g < 4; g++) {
                const unsigned long long* wp = wthr + (k * 4 + g) * 48;
                ulonglong2 w01 = *(const ulonglong2*)wp;
                ulonglong2 w23 = *(const ulonglong2*)(wp + 2);
                unsigned long long w4 = wp[4];
                FMA2(accp[g * 5 + 0], xv, w01.x);
                FMA2(accp[g * 5 + 1], xv, w01.y);
                FMA2(accp[g * 5 + 2], xv, w23.x);
                FMA2(accp[g * 5 + 3], xv, w23.y);
                FMA2(accp[g * 5 + 4], xv, w4);
            }
        }
        __syncthreads();   // before hbuf writes (aliases xs)

        // ---- gates + cell update (all in registers) ----
#pragma unroll
        for (int uu = 0; uu < 5; uu++) {
            int u = u0 + uu;
            float2 zi = u2f(accp[0 * 5 + uu]);
            float2 zf = u2f(accp[1 * 5 + uu]);
            float2 zc = u2f(accp[2 * 5 + uu]);
            float2 zo = u2f(accp[3 * 5 + uu]);
            size_t off = (size_t)u * P + base + 2 * tm;
            float2 cp = t0 ? make_float2(0.f, 0.f)
                           : *(const float2*)(g_c + off);
            float cn0 = fmaf(hsig(zf.x), cp.x, hsig(zi.x) * tanh_fma(zc.x));
            float cn1 = fmaf(hsig(zf.y), cp.y, hsig(zi.y) * tanh_fma(zc.y));
            float hn0 = hsig(zo.x) * tanh_fma(cn0);
            float hn1 = hsig(zo.y) * tanh_fma(cn1);
            *(float2*)(g_c + off) = make_float2(cn0, cn1);
            *(float2*)(g_h + off) = make_float2(hn0, hn1);
            hbuf[u * HB_STR + 2 * tm]     = hn0;
            hbuf[u * HB_STR + 2 * tm + 1] = hn1;
        }
        __syncthreads();

        // ---- f/i dots + param update (warp per 8 coords) ----
        for (int ci = 0; ci < 8; ci++) {
            int m = tn * 8 + ci;
            int coord = base + m;
            float hv = hbuf[tm * HB_STR + m];
            float pf = hv * Wf_s[tm];
            float pi = hv * Wi_s[tm];
            if (tm < 8) {
                float h2 = hbuf[(tm + 32) * HB_STR + m];
                pf = fmaf(h2, Wf_s[tm + 32], pf);
                pi = fmaf(h2, Wi_s[tm + 32], pi);
            }
#pragma unroll
            for (int off = 16; off > 0; off >>= 1) {
                pf += __shfl_xor_sync(0xffffffffu, pf, off);
                pi += __shfl_xor_sync(0xffffffffu, pi, off);
            }
            if (tm == 0) {
                float fprev = t0 ? 0.f : g_f[coord];
                float iprev = t0 ? 0.f : g_i[coord];
                float fnew = fmaxf(fmaf(fprev, Wf_s[40], pf) + bfv, 0.f);
                float inew = fmaxf(fmaf(iprev, Wi_s[40], pi) + biv, 0.f);
                float pold = t0 ? params[coord] : g_p[coord];
                float gv = g_grads[coord];
                float pnew = fnew * pold - inew * gv;
                g_f[coord] = fnew;
                g_i[coord] = inew;
                if (last) outp[coord] = pnew;
                else      g_p[coord] = pnew;
            }
        }
        __syncthreads();   // before next tile reuses xs/hbuf
    }
}

// ---------------------------------------------------------------------------
extern "C" void kernel_launch(void* const* d_in, const int* in_sizes, int n_in,
                              void* d_out, int out_size)
{
    const float* feats  = (const float*)d_in[0];
    const float* labels = (const float*)d_in[1];
    const float* params = (const float*)d_in[2];
    const float* kern   = (const float*)d_in[3];
    const float* rkern  = (const float*)d_in[4];
    const float* bias   = (const float*)d_in[5];
    const float* Wf     = (const float*)d_in[6];
    const float* bf     = (const float*)d_in[7];
    const float* Wi     = (const float*)d_in[8];
    const float* bi     = (const float*)d_in[9];
    float* out = (float*)d_out;

    cudaFuncSetAttribute(stepC, cudaFuncAttributeMaxDynamicSharedMemorySize,
                         SMEM_C_BYTES);

    for (int t = 0; t < T; t++) {
        const float* ft = feats  + (size_t)t * B * D;
        const float* lt = labels + (size_t)t * B * C;
        int t0 = (t == 0) ? 1 : 0;
        int last = (t == T - 1) ? 1 : 0;
        stepA<<<64, 256>>>(ft, lt, params, t0);
        stepB<<<128, 256>>>(ft);
        stepC<<<256, 256, SMEM_C_BYTES>>>(kern, rkern, bias, Wf, bf, Wi, bi,
                                          params, out, t0, last);
    }
}

// round 3
// speedup vs baseline: 1.5499x; 1.3509x over previous
#include <cuda_runtime.h>
#include <math.h>

// ---------------------------------------------------------------------------
// MetaLearner: coordinate-wise LSTM learned optimizer, 16 sequential steps.
// D=512, C=256, U=40, T=16, B=64, P=131072, 4 groups sharing weights.
// ---------------------------------------------------------------------------

#define D 512
#define C 256
#define U 40
#define T 16
#define B 64
#define P 131072
#define NZ 160              // 4*U
#define KE 43               // 3 + U   (l0,l1 folded into bias)
#define PREP 10.0f

#define NEGEXPP 4.5399929762484854e-05f   // exp(-10)
#define EXPP    22026.465794806718f       // exp(+10)

#define NBLK_C 148

// ---------------- persistent state (no allocations allowed) ----------------
__device__ float g_h[(size_t)U * P];     // transposed [U][P]
__device__ float g_c[(size_t)U * P];
__device__ float g_p[P];
__device__ float g_f[P];
__device__ float g_i[P];
__device__ __align__(16) float g_e[B * C];
__device__ float g_losspart[128];

// ---------------------------------------------------------------------------
// FMA/ALU-only tanh (no MUFU).
// ---------------------------------------------------------------------------
__device__ __forceinline__ float tanh_fma(float x)
{
    float xc = fminf(fmaxf(x, -9.0f), 9.0f);
    float y  = xc * 2.8853900817779268f;          // 2*log2(e)*x
    float r  = __fadd_rn(y, 12582912.0f);         // 1.5*2^23
    int   n  = __float_as_int(r) - 0x4B400000;
    float f  = y - __fadd_rn(r, -12582912.0f);    // f in [-0.5, 0.5]
    float p  = 1.5403530393e-4f;
    p = fmaf(p, f, 1.3333558146e-3f);
    p = fmaf(p, f, 9.6181291076e-3f);
    p = fmaf(p, f, 5.5504108665e-2f);
    p = fmaf(p, f, 2.4022650696e-1f);
    p = fmaf(p, f, 6.9314718056e-1f);
    p = fmaf(p, f, 1.0f);
    float e  = __int_as_float(__float_as_int(p) + (n << 23));  // exp(2x)
    float d  = e + 1.0f;
    float rc = __int_as_float(0x7EF311C3 - __float_as_int(d));
    rc = rc * fmaf(-d, rc, 2.0f);
    rc = rc * fmaf(-d, rc, 2.0f);
    rc = rc * fmaf(-d, rc, 2.0f);
    return fmaf(-2.0f, rc, 1.0f);                 // 1 - 2/(e+1)
}

__device__ __forceinline__ float hsig(float x)
{
    return __saturatef(fmaf(0.2f, x, 0.5f));
}

#define FMA2(acc, a, b) \
    asm("fma.rn.f32x2 %0, %1, %2, %0;" : "+l"(acc) : "l"(a), "l"(b))

__device__ __forceinline__ float2 u2f(unsigned long long v)
{
    float2 r;
    asm("mov.b64 {%0, %1}, %2;" : "=f"(r.x), "=f"(r.y) : "l"(v));
    return r;
}
__device__ __forceinline__ unsigned long long splat2(float w)
{
    unsigned int u = __float_as_uint(w);
    return (unsigned long long)u | ((unsigned long long)u << 32);
}

// ---------------------------------------------------------------------------
// Kernel A: preds/e/loss-partials.  grid 128 = b(64) x col-half(2), 256 thr.
// Threads: 32 col-quads x 8-way K split (64 d each).
// ---------------------------------------------------------------------------
__global__ void __launch_bounds__(256) stepA(
    const float* __restrict__ feats_t,
    const float* __restrict__ labels_t,
    const float* __restrict__ params, int t0)
{
    __shared__ float fr[D];
    __shared__ float4 sred[256];
    int tid = threadIdx.x;
    int b = blockIdx.x >> 1;
    int half = blockIdx.x & 1;

    fr[tid] = feats_t[b * D + tid];
    fr[tid + 256] = feats_t[b * D + tid + 256];
    __syncthreads();

    const float* pm = t0 ? params : g_p;
    const float4* pm4 = (const float4*)pm;
    int q = tid & 31;
    int c4 = half * 32 + q;
    int ks = tid >> 5;
    float4 acc = make_float4(0.f, 0.f, 0.f, 0.f);
    int dbeg = ks * 64;
#pragma unroll 8
    for (int d = dbeg; d < dbeg + 64; d++) {
        float fv = fr[d];
        float4 w = pm4[d * 64 + c4];
        acc.x = fmaf(fv, w.x, acc.x);
        acc.y = fmaf(fv, w.y, acc.y);
        acc.z = fmaf(fv, w.z, acc.z);
        acc.w = fmaf(fv, w.w, acc.w);
    }
    sred[tid] = acc;
    __syncthreads();

    if (tid < 32) {
        float4 s = sred[tid];
#pragma unroll
        for (int k = 1; k < 8; k++) {
            float4 a = sred[tid + 32 * k];
            s.x += a.x; s.y += a.y; s.z += a.z; s.w += a.w;
        }
        int cc = half * 32 + tid;
        float4 y = ((const float4*)labels_t)[b * 64 + cc];
        float4 df = make_float4(s.x - y.x, s.y - y.y, s.z - y.z, s.w - y.w);
        const float kc = 2.0f / 16384.0f;
        ((float4*)g_e)[b * 64 + cc] =
            make_float4(df.x * kc, df.y * kc, df.z * kc, df.w * kc);
        float v = df.x * df.x + df.y * df.y + df.z * df.z + df.w * df.w;
#pragma unroll
        for (int off = 16; off > 0; off >>= 1)
            v += __shfl_xor_sync(0xffffffffu, v, off);
        if (tid == 0) g_losspart[blockIdx.x] = v;
    }
}

// ---------------------------------------------------------------------------
// Kernel C: grads + LSTM + param update. grid = 148 blocks x 256 threads.
// Tiles of 64 coords; 2048 tiles distributed per group:
//   group tiles {256,512,768,512} -> blocks {19,37,55,37}.
// Per-block grads computed into smem from g_e + feats columns (stepB fused).
// Gate-aligned FFMA2 GEMM; f/i partials fused into gate phase.
// ---------------------------------------------------------------------------
#define WS2_ULL   (KE * 4 * 8 * 6)            // 8256 ull
#define ULL_TOT   (WS2_ULL + NZ)              // +biasEff = 8416 ull
#define F_WF      0
#define F_WI      41
#define F_SCAL    82
#define F_PAD     88                          // pad to even
#define F_FCOL    F_PAD                       // [5][64] = 320
#define F_GBUF    (F_FCOL + 320)              // 896
#define F_XS      (F_GBUF + 896)              // 43*66 = 2838  (even offset)
#define F_PR      (F_XS + KE * 66)            // float2[2][8][32] = 1024 floats
#define F_TOT     (F_PR + 1024)
#define XS_STR    66
#define SMEM_C_BYTES (ULL_TOT * 8 + F_TOT * 4)

__global__ void __launch_bounds__(256) stepC(
    const float* __restrict__ feats_t, // [64,512]
    const float* __restrict__ kern,    // [4,5,160]
    const float* __restrict__ rkern,   // [4,40,160]
    const float* __restrict__ bias,    // [4,160]
    const float* __restrict__ Wf,      // [4,41]
    const float* __restrict__ bf,      // [4]
    const float* __restrict__ Wi,      // [4,41]
    const float* __restrict__ bi,      // [4]
    const float* __restrict__ params,  // [P]
    float* __restrict__ outp,
    int t0, int last)
{
    extern __shared__ __align__(16) unsigned long long smU[];
    unsigned long long* Ws2 = smU;
    unsigned long long* biasEff2 = smU + WS2_ULL;
    float* smF  = (float*)(smU + ULL_TOT);
    float* Wf_s = smF + F_WF;
    float* Wi_s = smF + F_WI;
    float* scal = smF + F_SCAL;
    float* fcol = smF + F_FCOL;
    float* gbuf = smF + F_GBUF;
    float* xs   = smF + F_XS;
    float2* prF = (float2*)(smF + F_PR);          // [8][32]
    float2* prI = (float2*)(smF + F_PR + 512);    // [8][32]

    int tid = threadIdx.x;
    int blk = blockIdx.x;

    // ---- block -> (group, tile range) ----
    int grp, bi_, nb, nt, t0g;
    if (blk < 19)       { grp = 0; bi_ = blk;       nb = 19; nt = 256; t0g = 0;    }
    else if (blk < 56)  { grp = 1; bi_ = blk - 19;  nb = 37; nt = 512; t0g = 256;  }
    else if (blk < 111) { grp = 2; bi_ = blk - 56;  nb = 55; nt = 768; t0g = 768;  }
    else                { grp = 3; bi_ = blk - 111; nb = 37; nt = 512; t0g = 1536; }
    int q = nt / nb, r = nt % nb;
    int tile_start = t0g + bi_ * q + min(bi_, r);
    int ntiles = q + (bi_ < r ? 1 : 0);
    int start64 = tile_start * 64;
    int nc = ntiles * 64;

    // ---- phase 0a: weights, Wf/Wi, fcol, constants ----
    if (tid < 41) { Wf_s[tid] = Wf[grp * 41 + tid]; Wi_s[tid] = Wi[grp * 41 + tid]; }
    if (tid == 0) { scal[2] = bf[grp]; scal[3] = bi[grp]; }
    int d_lo = start64 >> 8;
    int d_hi = (start64 + nc - 1) >> 8;
    int nd = d_hi - d_lo + 1;                     // <= 5
    for (int idx = tid; idx < nd * 64; idx += 256) {
        int bb = idx & 63, k = idx >> 6;
        fcol[k * 64 + bb] = feats_t[bb * D + d_lo + k];
    }
    for (int idx = tid; idx < KE * NZ; idx += 256) {
        int k = idx / NZ, j = idx - k * NZ;
        int g = j / 40, rr = j - g * 40;
        int tn_ = rr / 5, uu = rr - tn_ * 5;
        float w = (k < 3) ? kern[grp * 800 + k * NZ + j]
                          : rkern[grp * 6400 + (k - 3) * NZ + j];
        Ws2[((k * 4 + g) * 8 + tn_) * 6 + uu] = splat2(w);
    }
    __syncthreads();

    // ---- phase 0b: loss reduce (warp 0) + grads into gbuf (all) ----
    if (tid < 32) {
        float v = g_losspart[tid] + g_losspart[tid + 32]
                + g_losspart[tid + 64] + g_losspart[tid + 96];
#pragma unroll
        for (int off = 16; off > 0; off >>= 1)
            v += __shfl_xor_sync(0xffffffffu, v, off);
        if (tid == 0) {
            float L = v * (1.0f / 16384.0f);
            float a = fabsf(L);
            if (a > NEGEXPP) {
                scal[0] = logf(a) / PREP;
                scal[1] = (L > 0.f) ? 1.f : ((L < 0.f) ? -1.f : 0.f);
            } else {
                scal[0] = -1.f;
                scal[1] = EXPP * L;
            }
        }
    }
    {
        int cc = (start64 + tid) & 255;
        float acc0 = 0.f, acc1 = 0.f, acc2 = 0.f, acc3 = 0.f;
        int dk0 = ((start64 + tid) >> 8) - d_lo;
        int dk1 = dk0 + 1, dk2 = dk0 + 2, dk3 = dk0 + 3;
        int n1 = nc - 256, n2 = nc - 512, n3 = nc - 768;
#pragma unroll 8
        for (int bb = 0; bb < B; bb++) {
            float ev = g_e[bb * C + cc];
            acc0 = fmaf(fcol[dk0 * 64 + bb], ev, acc0);
            if (tid < n1) acc1 = fmaf(fcol[dk1 * 64 + bb], ev, acc1);
            if (tid < n2) acc2 = fmaf(fcol[dk2 * 64 + bb], ev, acc2);
            if (tid < n3) acc3 = fmaf(fcol[dk3 * 64 + bb], ev, acc3);
        }
        gbuf[tid] = acc0;
        if (tid < n1) gbuf[tid + 256] = acc1;
        if (tid < n2) gbuf[tid + 512] = acc2;
        if (tid < n3) gbuf[tid + 768] = acc3;
    }
    __syncthreads();

    // ---- phase 0c: effective bias (l0,l1 folded), splatted ----
    float l0 = scal[0], l1 = scal[1], bfv = scal[2], biv = scal[3];
    if (tid < NZ) {
        float bval = bias[grp * NZ + tid]
                   + l0 * kern[grp * 800 + 3 * NZ + tid]
                   + l1 * kern[grp * 800 + 4 * NZ + tid];
        biasEff2[tid] = splat2(bval);
    }
    // (no barrier needed here: biasEff/gbuf consumed only after the per-tile
    //  fill barrier below)

    int tm = tid & 31;            // coord pair (2tm, 2tm+1)
    int tn = tid >> 5;            // u-range tn*5..tn*5+4
    int u0 = tn * 5;
    const unsigned long long* wthr = Ws2 + tn * 6;

    for (int it = 0; it < ntiles; it++) {
        int base = start64 + it * 64;
        int rel = it * 64;

        // ---- fill xs ----
        if (tid < 64) {
            int coord = base + tid;
            float pv = t0 ? params[coord] : g_p[coord];
            float gv = gbuf[rel + tid];
            float a = fabsf(gv);
            float g0, g1;
            if (a > NEGEXPP) {
                g0 = logf(a) / PREP;
                g1 = (gv > 0.f) ? 1.f : ((gv < 0.f) ? -1.f : 0.f);
            } else {
                g0 = -1.f;
                g1 = EXPP * gv;
            }
            xs[0 * XS_STR + tid] = pv;
            xs[1 * XS_STR + tid] = g0;
            xs[2 * XS_STR + tid] = g1;
        }
        if (t0) {
            for (int idx = tid; idx < 64 * U; idx += 256) {
                int u = idx >> 6, m = idx & 63;
                xs[(3 + u) * XS_STR + m] = 0.f;
            }
        } else {
            for (int idx = tid; idx < 64 * U; idx += 256) {
                int u = idx >> 6, m = idx & 63;
                xs[(3 + u) * XS_STR + m] = g_h[(size_t)u * P + base + m];
            }
        }
        __syncthreads();

        // ---- GEMM: z = x @ W + biasEff (FFMA2, gate-aligned) ----
        unsigned long long accp[20];
#pragma unroll
        for (int g = 0; g < 4; g++)
#pragma unroll
            for (int uu = 0; uu < 5; uu++)
                accp[g * 5 + uu] = biasEff2[g * 40 + u0 + uu];

#pragma unroll 2
        for (int k = 0; k < KE; k++) {
            unsigned long long xv =
                *(const unsigned long long*)(xs + k * XS_STR + 2 * tm);
#pragma unroll
            for (int g = 0; g < 4; g++) {
                const unsigned long long* wp = wthr + (k * 4 + g) * 48;
                ulonglong2 w01 = *(const ulonglong2*)wp;
                ulonglong2 w23 = *(const ulonglong2*)(wp + 2);
                unsigned long long w4 = wp[4];
                FMA2(accp[g * 5 + 0], xv, w01.x);
                FMA2(accp[g * 5 + 1], xv, w01.y);
                FMA2(accp[g * 5 + 2], xv, w23.x);
                FMA2(accp[g * 5 + 3], xv, w23.y);
                FMA2(accp[g * 5 + 4], xv, w4);
            }
        }

        // ---- gates + cell update + f/i partials (registers) ----
        float pf0 = 0.f, pf1 = 0.f, pi0 = 0.f, pi1 = 0.f;
#pragma unroll
        for (int uu = 0; uu < 5; uu++) {
            int u = u0 + uu;
            float2 zi = u2f(accp[0 * 5 + uu]);
            float2 zf = u2f(accp[1 * 5 + uu]);
            float2 zc = u2f(accp[2 * 5 + uu]);
            float2 zo = u2f(accp[3 * 5 + uu]);
            size_t off = (size_t)u * P + base + 2 * tm;
            float2 cp = t0 ? make_float2(0.f, 0.f)
                           : *(const float2*)(g_c + off);
            float cn0 = fmaf(hsig(zf.x), cp.x, hsig(zi.x) * tanh_fma(zc.x));
            float cn1 = fmaf(hsig(zf.y), cp.y, hsig(zi.y) * tanh_fma(zc.y));
            float hn0 = hsig(zo.x) * tanh_fma(cn0);
            float hn1 = hsig(zo.y) * tanh_fma(cn1);
            *(float2*)(g_c + off) = make_float2(cn0, cn1);
            *(float2*)(g_h + off) = make_float2(hn0, hn1);
            float wf = Wf_s[u], wi = Wi_s[u];
            pf0 = fmaf(hn0, wf, pf0);
            pf1 = fmaf(hn1, wf, pf1);
            pi0 = fmaf(hn0, wi, pi0);
            pi1 = fmaf(hn1, wi, pi1);
        }
        prF[tn * 32 + tm] = make_float2(pf0, pf1);
        prI[tn * 32 + tm] = make_float2(pi0, pi1);
        __syncthreads();

        // ---- reduce partials + param update (tid < 64) ----
        if (tid < 64) {
            int m = tid;
            int coord = base + m;
            int half_ = m & 1, mp = m >> 1;
            float pf = 0.f, pi = 0.f;
#pragma unroll
            for (int w = 0; w < 8; w++) {
                float2 vf = prF[w * 32 + mp];
                float2 vi = prI[w * 32 + mp];
                pf += half_ ? vf.y : vf.x;
                pi += half_ ? vi.y : vi.x;
            }
            float fprev = t0 ? 0.f : g_f[coord];
            float iprev = t0 ? 0.f : g_i[coord];
            float fnew = fmaxf(fmaf(fprev, Wf_s[40], pf) + bfv, 0.f);
            float inew = fmaxf(fmaf(iprev, Wi_s[40], pi) + biv, 0.f);
            float pold = xs[0 * XS_STR + m];
            float gv = gbuf[rel + m];
            float pnew = fnew * pold - inew * gv;
            g_f[coord] = fnew;
            g_i[coord] = inew;
            if (last) outp[coord] = pnew;
            else      g_p[coord] = pnew;
        }
        __syncthreads();   // before next tile reuses xs/prF/prI
    }
}

// ---------------------------------------------------------------------------
extern "C" void kernel_launch(void* const* d_in, const int* in_sizes, int n_in,
                              void* d_out, int out_size)
{
    const float* feats  = (const float*)d_in[0];
    const float* labels = (const float*)d_in[1];
    const float* params = (const float*)d_in[2];
    const float* kern   = (const float*)d_in[3];
    const float* rkern  = (const float*)d_in[4];
    const float* bias   = (const float*)d_in[5];
    const float* Wf     = (const float*)d_in[6];
    const float* bf     = (const float*)d_in[7];
    const float* Wi     = (const float*)d_in[8];
    const float* bi     = (const float*)d_in[9];
    float* out = (float*)d_out;

    cudaFuncSetAttribute(stepC, cudaFuncAttributeMaxDynamicSharedMemorySize,
                         SMEM_C_BYTES);

    for (int t = 0; t < T; t++) {
        const float* ft = feats  + (size_t)t * B * D;
        const float* lt = labels + (size_t)t * B * C;
        int t0 = (t == 0) ? 1 : 0;
        int last = (t == T - 1) ? 1 : 0;
        stepA<<<128, 256>>>(ft, lt, params, t0);
        stepC<<<NBLK_C, 256, SMEM_C_BYTES>>>(ft, kern, rkern, bias,
                                             Wf, bf, Wi, bi,
                                             params, out, t0, last);
    }
}

// round 4
// speedup vs baseline: 1.8460x; 1.1910x over previous
#include <cuda_runtime.h>
#include <math.h>

// ---------------------------------------------------------------------------
// MetaLearner: coordinate-wise LSTM learned optimizer, 16 sequential steps.
// D=512, C=256, U=40, T=16, B=64, P=131072, 4 groups sharing weights.
// ---------------------------------------------------------------------------

#define D 512
#define C 256
#define U 40
#define T 16
#define B 64
#define P 131072
#define NZ 160              // 4*U
#define KE 43               // 3 + U   (l0,l1 folded into bias)
#define PREP 10.0f

#define NEGEXPP 4.5399929762484854e-05f   // exp(-10)
#define EXPP    22026.465794806718f       // exp(+10)

#define NBLK_C 296          // 2 blocks per SM

// ---------------- persistent state (no allocations allowed) ----------------
__device__ float g_h[(size_t)U * P];     // transposed [U][P]
__device__ float g_c[(size_t)U * P];
__device__ float g_p[P];
__device__ float g_f[P];
__device__ float g_i[P];
__device__ __align__(16) float g_e[B * C];
__device__ float g_losspart[128];

// ---------------------------------------------------------------------------
// FMA/ALU-only tanh (no MUFU).
// ---------------------------------------------------------------------------
__device__ __forceinline__ float tanh_fma(float x)
{
    float xc = fminf(fmaxf(x, -9.0f), 9.0f);
    float y  = xc * 2.8853900817779268f;          // 2*log2(e)*x
    float r  = __fadd_rn(y, 12582912.0f);         // 1.5*2^23
    int   n  = __float_as_int(r) - 0x4B400000;
    float f  = y - __fadd_rn(r, -12582912.0f);    // f in [-0.5, 0.5]
    float p  = 1.5403530393e-4f;
    p = fmaf(p, f, 1.3333558146e-3f);
    p = fmaf(p, f, 9.6181291076e-3f);
    p = fmaf(p, f, 5.5504108665e-2f);
    p = fmaf(p, f, 2.4022650696e-1f);
    p = fmaf(p, f, 6.9314718056e-1f);
    p = fmaf(p, f, 1.0f);
    float e  = __int_as_float(__float_as_int(p) + (n << 23));  // exp(2x)
    float d  = e + 1.0f;
    float rc = __int_as_float(0x7EF311C3 - __float_as_int(d));
    rc = rc * fmaf(-d, rc, 2.0f);
    rc = rc * fmaf(-d, rc, 2.0f);
    rc = rc * fmaf(-d, rc, 2.0f);
    return fmaf(-2.0f, rc, 1.0f);                 // 1 - 2/(e+1)
}

__device__ __forceinline__ float hsig(float x)
{
    return __saturatef(fmaf(0.2f, x, 0.5f));
}

#define FMA2(acc, a, b) \
    asm("fma.rn.f32x2 %0, %1, %2, %0;" : "+l"(acc) : "l"(a), "l"(b))

__device__ __forceinline__ float2 u2f(unsigned long long v)
{
    float2 r;
    asm("mov.b64 {%0, %1}, %2;" : "=f"(r.x), "=f"(r.y) : "l"(v));
    return r;
}
__device__ __forceinline__ unsigned long long splat2(float w)
{
    unsigned int u = __float_as_uint(w);
    return (unsigned long long)u | ((unsigned long long)u << 32);
}

// ---------------------------------------------------------------------------
// Kernel A: preds/e/loss-partials.  grid 128 = b(64) x col-half(2), 256 thr.
// ---------------------------------------------------------------------------
__global__ void __launch_bounds__(256) stepA(
    const float* __restrict__ feats_t,
    const float* __restrict__ labels_t,
    const float* __restrict__ params, int t0)
{
    __shared__ float fr[D];
    __shared__ float4 sred[256];
    int tid = threadIdx.x;
    int b = blockIdx.x >> 1;
    int half = blockIdx.x & 1;

    fr[tid] = feats_t[b * D + tid];
    fr[tid + 256] = feats_t[b * D + tid + 256];
    __syncthreads();

    const float* pm = t0 ? params : g_p;
    const float4* pm4 = (const float4*)pm;
    int q = tid & 31;
    int c4 = half * 32 + q;
    int ks = tid >> 5;
    float4 acc = make_float4(0.f, 0.f, 0.f, 0.f);
    int dbeg = ks * 64;
#pragma unroll 8
    for (int d = dbeg; d < dbeg + 64; d++) {
        float fv = fr[d];
        float4 w = pm4[d * 64 + c4];
        acc.x = fmaf(fv, w.x, acc.x);
        acc.y = fmaf(fv, w.y, acc.y);
        acc.z = fmaf(fv, w.z, acc.z);
        acc.w = fmaf(fv, w.w, acc.w);
    }
    sred[tid] = acc;
    __syncthreads();

    if (tid < 32) {
        float4 s = sred[tid];
#pragma unroll
        for (int k = 1; k < 8; k++) {
            float4 a = sred[tid + 32 * k];
            s.x += a.x; s.y += a.y; s.z += a.z; s.w += a.w;
        }
        int cc = half * 32 + tid;
        float4 y = ((const float4*)labels_t)[b * 64 + cc];
        float4 df = make_float4(s.x - y.x, s.y - y.y, s.z - y.z, s.w - y.w);
        const float kc = 2.0f / 16384.0f;
        ((float4*)g_e)[b * 64 + cc] =
            make_float4(df.x * kc, df.y * kc, df.z * kc, df.w * kc);
        float v = df.x * df.x + df.y * df.y + df.z * df.z + df.w * df.w;
#pragma unroll
        for (int off = 16; off > 0; off >>= 1)
            v += __shfl_xor_sync(0xffffffffu, v, off);
        if (tid == 0) g_losspart[blockIdx.x] = v;
    }
}

// ---------------------------------------------------------------------------
// Kernel C: grads + LSTM + param update. grid = 296 blocks (2/SM) x 256 thr.
// 2048 tiles of 64 coords distributed per group:
//   group tiles {256,512,768,512} -> blocks {37,74,111,74}.
// ---------------------------------------------------------------------------
#define WS2_ULL   (KE * 4 * 8 * 6)            // 8256 ull
#define ULL_TOT   (WS2_ULL + NZ)              // +biasEff = 8416 ull
#define F_WF      0
#define F_WI      41
#define F_SCAL    82
#define F_PAD     88
#define F_FCOL    F_PAD                       // [5][64] = 320
#define F_GBUF    (F_FCOL + 320)              // 512 floats enough (nc<=448)
#define F_XS      (F_GBUF + 512)
#define F_PR      (F_XS + KE * 66)            // float2[2][8][32] = 1024 floats
#define F_TOT     (F_PR + 1024)
#define XS_STR    66
#define SMEM_C_BYTES (ULL_TOT * 8 + F_TOT * 4)

__global__ void __launch_bounds__(256) stepC(
    const float* __restrict__ feats_t, // [64,512]
    const float* __restrict__ kern,    // [4,5,160]
    const float* __restrict__ rkern,   // [4,40,160]
    const float* __restrict__ bias,    // [4,160]
    const float* __restrict__ Wf,      // [4,41]
    const float* __restrict__ bf,      // [4]
    const float* __restrict__ Wi,      // [4,41]
    const float* __restrict__ bi,      // [4]
    const float* __restrict__ params,  // [P]
    float* __restrict__ outp,
    int t0, int last)
{
    extern __shared__ __align__(16) unsigned long long smU[];
    unsigned long long* Ws2 = smU;
    unsigned long long* biasEff2 = smU + WS2_ULL;
    float* smF  = (float*)(smU + ULL_TOT);
    float* Wf_s = smF + F_WF;
    float* Wi_s = smF + F_WI;
    float* scal = smF + F_SCAL;
    float* fcol = smF + F_FCOL;
    float* gbuf = smF + F_GBUF;
    float* xs   = smF + F_XS;
    float2* prF = (float2*)(smF + F_PR);          // [8][32]
    float2* prI = (float2*)(smF + F_PR + 512);    // [8][32]

    int tid = threadIdx.x;
    int blk = blockIdx.x;

    // ---- block -> (group, tile range) ----
    int grp, bi_, nb, nt, t0g;
    if (blk < 37)       { grp = 0; bi_ = blk;       nb = 37;  nt = 256; t0g = 0;    }
    else if (blk < 111) { grp = 1; bi_ = blk - 37;  nb = 74;  nt = 512; t0g = 256;  }
    else if (blk < 222) { grp = 2; bi_ = blk - 111; nb = 111; nt = 768; t0g = 768;  }
    else                { grp = 3; bi_ = blk - 222; nb = 74;  nt = 512; t0g = 1536; }
    int q = nt / nb, r = nt % nb;
    int tile_start = t0g + bi_ * q + min(bi_, r);
    int ntiles = q + (bi_ < r ? 1 : 0);          // 6 or 7
    int start64 = tile_start * 64;
    int nc = ntiles * 64;                        // <= 448

    // ---- phase 0a: weights, Wf/Wi, fcol, constants ----
    if (tid < 41) { Wf_s[tid] = Wf[grp * 41 + tid]; Wi_s[tid] = Wi[grp * 41 + tid]; }
    if (tid == 0) { scal[2] = bf[grp]; scal[3] = bi[grp]; }
    int d_lo = start64 >> 8;
    int d_hi = (start64 + nc - 1) >> 8;
    int nd = d_hi - d_lo + 1;                     // <= 3
    for (int idx = tid; idx < nd * 64; idx += 256) {
        int bb = idx & 63, k = idx >> 6;
        fcol[k * 64 + bb] = feats_t[bb * D + d_lo + k];
    }
    for (int idx = tid; idx < KE * NZ; idx += 256) {
        int k = idx / NZ, j = idx - k * NZ;
        int g = j / 40, rr = j - g * 40;
        int tn_ = rr / 5, uu = rr - tn_ * 5;
        float w = (k < 3) ? kern[grp * 800 + k * NZ + j]
                          : rkern[grp * 6400 + (k - 3) * NZ + j];
        Ws2[((k * 4 + g) * 8 + tn_) * 6 + uu] = splat2(w);
    }
    __syncthreads();

    // ---- phase 0b: loss reduce (warp 0) + grads into gbuf (all) ----
    if (tid < 32) {
        float v = g_losspart[tid] + g_losspart[tid + 32]
                + g_losspart[tid + 64] + g_losspart[tid + 96];
#pragma unroll
        for (int off = 16; off > 0; off >>= 1)
            v += __shfl_xor_sync(0xffffffffu, v, off);
        if (tid == 0) {
            float L = v * (1.0f / 16384.0f);
            float a = fabsf(L);
            if (a > NEGEXPP) {
                scal[0] = logf(a) / PREP;
                scal[1] = (L > 0.f) ? 1.f : ((L < 0.f) ? -1.f : 0.f);
            } else {
                scal[0] = -1.f;
                scal[1] = EXPP * L;
            }
        }
    }
    {
        int cc = (start64 + tid) & 255;
        float acc0 = 0.f, acc1 = 0.f;
        int dk0 = ((start64 + tid) >> 8) - d_lo;
        int dk1 = dk0 + 1;
        int n1 = nc - 256;
#pragma unroll 8
        for (int bb = 0; bb < B; bb++) {
            float ev = g_e[bb * C + cc];
            acc0 = fmaf(fcol[dk0 * 64 + bb], ev, acc0);
            if (tid < n1) acc1 = fmaf(fcol[dk1 * 64 + bb], ev, acc1);
        }
        gbuf[tid] = acc0;
        if (tid < n1) gbuf[tid + 256] = acc1;
    }
    __syncthreads();

    // ---- phase 0c: effective bias (l0,l1 folded), splatted ----
    float l0 = scal[0], l1 = scal[1], bfv = scal[2], biv = scal[3];
    if (tid < NZ) {
        float bval = bias[grp * NZ + tid]
                   + l0 * kern[grp * 800 + 3 * NZ + tid]
                   + l1 * kern[grp * 800 + 4 * NZ + tid];
        biasEff2[tid] = splat2(bval);
    }

    int tm = tid & 31;            // coord pair (2tm, 2tm+1)
    int tn = tid >> 5;            // u-range tn*5..tn*5+4
    int u0 = tn * 5;
    const unsigned long long* wthr = Ws2 + tn * 6;

    for (int it = 0; it < ntiles; it++) {
        int base = start64 + it * 64;
        int rel = it * 64;

        // ---- fill xs ----
        if (tid < 64) {
            int coord = base + tid;
            float pv = t0 ? params[coord] : g_p[coord];
            float gv = gbuf[rel + tid];
            float a = fabsf(gv);
            float g0, g1;
            if (a > NEGEXPP) {
                g0 = logf(a) / PREP;
                g1 = (gv > 0.f) ? 1.f : ((gv < 0.f) ? -1.f : 0.f);
            } else {
                g0 = -1.f;
                g1 = EXPP * gv;
            }
            xs[0 * XS_STR + tid] = pv;
            xs[1 * XS_STR + tid] = g0;
            xs[2 * XS_STR + tid] = g1;
        }
        if (t0) {
            for (int idx = tid; idx < 32 * U; idx += 256) {
                int u = idx >> 5, m2 = idx & 31;
                *(float2*)(xs + (3 + u) * XS_STR + 2 * m2) = make_float2(0.f, 0.f);
            }
        } else {
            for (int idx = tid; idx < 32 * U; idx += 256) {
                int u = idx >> 5, m2 = idx & 31;
                float2 hv = *(const float2*)(g_h + (size_t)u * P + base + 2 * m2);
                *(float2*)(xs + (3 + u) * XS_STR + 2 * m2) = hv;
            }
        }
        __syncthreads();

        // ---- GEMM: z = x @ W + biasEff (FFMA2, gate-aligned) ----
        unsigned long long accp[20];
#pragma unroll
        for (int g = 0; g < 4; g++)
#pragma unroll
            for (int uu = 0; uu < 5; uu++)
                accp[g * 5 + uu] = biasEff2[g * 40 + u0 + uu];

#pragma unroll 2
        for (int k = 0; k < KE; k++) {
            unsigned long long xv =
                *(const unsigned long long*)(xs + k * XS_STR + 2 * tm);
#pragma unroll
            for (int g = 0; g < 4; g++) {
                const unsigned long long* wp = wthr + (k * 4 + g) * 48;
                ulonglong2 w01 = *(const ulonglong2*)wp;
                ulonglong2 w23 = *(const ulonglong2*)(wp + 2);
                unsigned long long w4 = wp[4];
                FMA2(accp[g * 5 + 0], xv, w01.x);
                FMA2(accp[g * 5 + 1], xv, w01.y);
                FMA2(accp[g * 5 + 2], xv, w23.x);
                FMA2(accp[g * 5 + 3], xv, w23.y);
                FMA2(accp[g * 5 + 4], xv, w4);
            }
        }

        // ---- gates + cell update + f/i partials (registers) ----
        float pf0 = 0.f, pf1 = 0.f, pi0 = 0.f, pi1 = 0.f;
#pragma unroll
        for (int uu = 0; uu < 5; uu++) {
            int u = u0 + uu;
            float2 zi = u2f(accp[0 * 5 + uu]);
            float2 zf = u2f(accp[1 * 5 + uu]);
            float2 zc = u2f(accp[2 * 5 + uu]);
            float2 zo = u2f(accp[3 * 5 + uu]);
            size_t off = (size_t)u * P + base + 2 * tm;
            float2 cp = t0 ? make_float2(0.f, 0.f)
                           : *(const float2*)(g_c + off);
            float cn0 = fmaf(hsig(zf.x), cp.x, hsig(zi.x) * tanh_fma(zc.x));
            float cn1 = fmaf(hsig(zf.y), cp.y, hsig(zi.y) * tanh_fma(zc.y));
            float hn0 = hsig(zo.x) * tanh_fma(cn0);
            float hn1 = hsig(zo.y) * tanh_fma(cn1);
            *(float2*)(g_c + off) = make_float2(cn0, cn1);
            *(float2*)(g_h + off) = make_float2(hn0, hn1);
            float wf = Wf_s[u], wi = Wi_s[u];
            pf0 = fmaf(hn0, wf, pf0);
            pf1 = fmaf(hn1, wf, pf1);
            pi0 = fmaf(hn0, wi, pi0);
            pi1 = fmaf(hn1, wi, pi1);
        }
        prF[tn * 32 + tm] = make_float2(pf0, pf1);
        prI[tn * 32 + tm] = make_float2(pi0, pi1);
        __syncthreads();

        // ---- reduce partials + param update (tid < 64) ----
        if (tid < 64) {
            int m = tid;
            int coord = base + m;
            int half_ = m & 1, mp = m >> 1;
            float pf = 0.f, pi = 0.f;
#pragma unroll
            for (int w = 0; w < 8; w++) {
                float2 vf = prF[w * 32 + mp];
                float2 vi = prI[w * 32 + mp];
                pf += half_ ? vf.y : vf.x;
                pi += half_ ? vi.y : vi.x;
            }
            float fprev = t0 ? 0.f : g_f[coord];
            float iprev = t0 ? 0.f : g_i[coord];
            float fnew = fmaxf(fmaf(fprev, Wf_s[40], pf) + bfv, 0.f);
            float inew = fmaxf(fmaf(iprev, Wi_s[40], pi) + biv, 0.f);
            float pold = xs[0 * XS_STR + m];
            float gv = gbuf[rel + m];
            float pnew = fnew * pold - inew * gv;
            g_f[coord] = fnew;
            g_i[coord] = inew;
            if (last) outp[coord] = pnew;
            else      g_p[coord] = pnew;
        }
        __syncthreads();   // before next tile reuses xs/prF/prI
    }
}

// ---------------------------------------------------------------------------
extern "C" void kernel_launch(void* const* d_in, const int* in_sizes, int n_in,
                              void* d_out, int out_size)
{
    const float* feats  = (const float*)d_in[0];
    const float* labels = (const float*)d_in[1];
    const float* params = (const float*)d_in[2];
    const float* kern   = (const float*)d_in[3];
    const float* rkern  = (const float*)d_in[4];
    const float* bias   = (const float*)d_in[5];
    const float* Wf     = (const float*)d_in[6];
    const float* bf     = (const float*)d_in[7];
    const float* Wi     = (const float*)d_in[8];
    const float* bi     = (const float*)d_in[9];
    float* out = (float*)d_out;

    cudaFuncSetAttribute(stepC, cudaFuncAttributeMaxDynamicSharedMemorySize,
                         SMEM_C_BYTES);

    for (int t = 0; t < T; t++) {
        const float* ft = feats  + (size_t)t * B * D;
        const float* lt = labels + (size_t)t * B * C;
        int t0 = (t == 0) ? 1 : 0;
        int last = (t == T - 1) ? 1 : 0;
        stepA<<<128, 256>>>(ft, lt, params, t0);
        stepC<<<NBLK_C, 256, SMEM_C_BYTES>>>(ft, kern, rkern, bias,
                                             Wf, bf, Wi, bi,
                                             params, out, t0, last);
    }
}

// round 5
// speedup vs baseline: 2.1533x; 1.1664x over previous
#include <cuda_runtime.h>
#include <math.h>

// ---------------------------------------------------------------------------
// MetaLearner: coordinate-wise LSTM learned optimizer, 16 sequential steps.
// D=512, C=256, U=40, T=16, B=64, P=131072, 4 groups sharing weights.
// ---------------------------------------------------------------------------

#define D 512
#define C 256
#define U 40
#define T 16
#define B 64
#define P 131072
#define NZ 160              // 4*U
#define KE 43               // 3 + U   (l0,l1 folded into bias)
#define PREP 10.0f

#define NEGEXPP 4.5399929762484854e-05f   // exp(-10)
#define EXPP    22026.465794806718f       // exp(+10)

#define NBLK_C 444          // 3 blocks per SM

// ---------------- persistent state (no allocations allowed) ----------------
__device__ float g_h[(size_t)U * P];     // transposed [U][P]
__device__ float g_c[(size_t)U * P];
__device__ float g_p[P];
__device__ float g_f[P];
__device__ float g_i[P];
__device__ __align__(16) float g_e[B * C];
__device__ float g_losspart[128];

// ---------------------------------------------------------------------------
// FMA/ALU-only tanh (no MUFU).
// ---------------------------------------------------------------------------
__device__ __forceinline__ float tanh_fma(float x)
{
    float xc = fminf(fmaxf(x, -9.0f), 9.0f);
    float y  = xc * 2.8853900817779268f;          // 2*log2(e)*x
    float r  = __fadd_rn(y, 12582912.0f);         // 1.5*2^23
    int   n  = __float_as_int(r) - 0x4B400000;
    float f  = y - __fadd_rn(r, -12582912.0f);    // f in [-0.5, 0.5]
    float p  = 1.5403530393e-4f;
    p = fmaf(p, f, 1.3333558146e-3f);
    p = fmaf(p, f, 9.6181291076e-3f);
    p = fmaf(p, f, 5.5504108665e-2f);
    p = fmaf(p, f, 2.4022650696e-1f);
    p = fmaf(p, f, 6.9314718056e-1f);
    p = fmaf(p, f, 1.0f);
    float e  = __int_as_float(__float_as_int(p) + (n << 23));  // exp(2x)
    float d  = e + 1.0f;
    float rc = __int_as_float(0x7EF311C3 - __float_as_int(d));
    rc = rc * fmaf(-d, rc, 2.0f);
    rc = rc * fmaf(-d, rc, 2.0f);
    rc = rc * fmaf(-d, rc, 2.0f);
    return fmaf(-2.0f, rc, 1.0f);                 // 1 - 2/(e+1)
}

__device__ __forceinline__ float hsig(float x)
{
    return __saturatef(fmaf(0.2f, x, 0.5f));
}

#define FMA2(acc, a, b) \
    asm("fma.rn.f32x2 %0, %1, %2, %0;" : "+l"(acc) : "l"(a), "l"(b))

__device__ __forceinline__ float2 u2f(unsigned long long v)
{
    float2 r;
    asm("mov.b64 {%0, %1}, %2;" : "=f"(r.x), "=f"(r.y) : "l"(v));
    return r;
}
__device__ __forceinline__ unsigned long long pack2(float a, float b)
{
    unsigned long long v;
    asm("mov.b64 %0, {%1, %2};" : "=l"(v) : "f"(a), "f"(b));
    return v;
}

// ---------------------------------------------------------------------------
// Kernel A: preds/e/loss-partials.  grid 128 = b(64) x col-half(2), 256 thr.
// ---------------------------------------------------------------------------
__global__ void __launch_bounds__(256) stepA(
    const float* __restrict__ feats_t,
    const float* __restrict__ labels_t,
    const float* __restrict__ params, int t0)
{
    __shared__ float fr[D];
    __shared__ float4 sred[256];
    int tid = threadIdx.x;
    int b = blockIdx.x >> 1;
    int half = blockIdx.x & 1;

    fr[tid] = feats_t[b * D + tid];
    fr[tid + 256] = feats_t[b * D + tid + 256];
    __syncthreads();

    const float* pm = t0 ? params : g_p;
    const float4* pm4 = (const float4*)pm;
    int q = tid & 31;
    int c4 = half * 32 + q;
    int ks = tid >> 5;
    float4 acc = make_float4(0.f, 0.f, 0.f, 0.f);
    int dbeg = ks * 64;
#pragma unroll 8
    for (int d = dbeg; d < dbeg + 64; d++) {
        float fv = fr[d];
        float4 w = pm4[d * 64 + c4];
        acc.x = fmaf(fv, w.x, acc.x);
        acc.y = fmaf(fv, w.y, acc.y);
        acc.z = fmaf(fv, w.z, acc.z);
        acc.w = fmaf(fv, w.w, acc.w);
    }
    sred[tid] = acc;
    __syncthreads();

    if (tid < 32) {
        float4 s = sred[tid];
#pragma unroll
        for (int k = 1; k < 8; k++) {
            float4 a = sred[tid + 32 * k];
            s.x += a.x; s.y += a.y; s.z += a.z; s.w += a.w;
        }
        int cc = half * 32 + tid;
        float4 y = ((const float4*)labels_t)[b * 64 + cc];
        float4 df = make_float4(s.x - y.x, s.y - y.y, s.z - y.z, s.w - y.w);
        const float kc = 2.0f / 16384.0f;
        ((float4*)g_e)[b * 64 + cc] =
            make_float4(df.x * kc, df.y * kc, df.z * kc, df.w * kc);
        float v = df.x * df.x + df.y * df.y + df.z * df.z + df.w * df.w;
#pragma unroll
        for (int off = 16; off > 0; off >>= 1)
            v += __shfl_xor_sync(0xffffffffu, v, off);
        if (tid == 0) g_losspart[blockIdx.x] = v;
    }
}

// ---------------------------------------------------------------------------
// Kernel C: grads + LSTM + param update. grid = 444 blocks (3/SM) x 256 thr.
// 2048 tiles of 64 coords distributed per group:
//   group tiles {256,512,768,512} -> blocks {56,111,166,111}.
// Gate-paired FFMA2: acc = (z_i, z_f) / (z_c, z_o); weights stored unsplatted
// as pairs, x splatted per coord.  3 barriers/tile.
// ---------------------------------------------------------------------------
#define WP_ULL    (KE * 8 * 10)              // 3440 ull weight pairs
#define ULL_TOT   (WP_ULL + 80)              // + bias pairs = 3520 ull
#define F_WF      0
#define F_WI      41
#define F_SCAL    82
#define F_FCOL    88                          // [3][64] = 192
#define F_GBUF    (F_FCOL + 192)              // 320 floats (nc<=320)
#define F_XS      (F_GBUF + 320)              // 600 (even -> 8B aligned)
#define XS_STR    66
#define F_PR      (F_XS + KE * XS_STR)        // 600+2838=3438 (even)
#define F_TOT     (F_PR + 1024)
#define SMEM_C_BYTES (ULL_TOT * 8 + F_TOT * 4)   // 28160+17848=46008

__global__ void __launch_bounds__(256, 3) stepC(
    const float* __restrict__ feats_t, // [64,512]
    const float* __restrict__ kern,    // [4,5,160]
    const float* __restrict__ rkern,   // [4,40,160]
    const float* __restrict__ bias,    // [4,160]
    const float* __restrict__ Wf,      // [4,41]
    const float* __restrict__ bf,      // [4]
    const float* __restrict__ Wi,      // [4,41]
    const float* __restrict__ bi,      // [4]
    const float* __restrict__ params,  // [P]
    float* __restrict__ outp,
    int t0, int last)
{
    extern __shared__ __align__(16) unsigned long long smU[];
    unsigned long long* Wp  = smU;            // [43][8][10]
    unsigned long long* bp  = smU + WP_ULL;   // [8][10]
    float* smF  = (float*)(smU + ULL_TOT);
    float* Wf_s = smF + F_WF;
    float* Wi_s = smF + F_WI;
    float* scal = smF + F_SCAL;
    float* fcol = smF + F_FCOL;
    float* gbuf = smF + F_GBUF;
    float* xs   = smF + F_XS;
    float2* prF = (float2*)(smF + F_PR);          // [8][32]
    float2* prI = (float2*)(smF + F_PR + 512);    // [8][32]

    int tid = threadIdx.x;
    int blk = blockIdx.x;

    // ---- block -> (group, tile range) ----
    int grp, bi_, nb, nt, t0g;
    if (blk < 56)       { grp = 0; bi_ = blk;       nb = 56;  nt = 256; t0g = 0;    }
    else if (blk < 167) { grp = 1; bi_ = blk - 56;  nb = 111; nt = 512; t0g = 256;  }
    else if (blk < 333) { grp = 2; bi_ = blk - 167; nb = 166; nt = 768; t0g = 768;  }
    else                { grp = 3; bi_ = blk - 333; nb = 111; nt = 512; t0g = 1536; }
    int q = nt / nb, r = nt % nb;
    int tile_start = t0g + bi_ * q + min(bi_, r);
    int ntiles = q + (bi_ < r ? 1 : 0);          // 4 or 5
    int start64 = tile_start * 64;
    int nc = ntiles * 64;                        // <= 320

    // ---- phase 0a: weights (gate-paired), Wf/Wi, fcol, constants ----
    if (tid < 41) { Wf_s[tid] = Wf[grp * 41 + tid]; Wi_s[tid] = Wi[grp * 41 + tid]; }
    if (tid == 0) { scal[2] = bf[grp]; scal[3] = bi[grp]; }
    int d_lo = start64 >> 8;
    int d_hi = (start64 + nc - 1) >> 8;
    int nd = d_hi - d_lo + 1;                     // <= 3
    for (int idx = tid; idx < nd * 64; idx += 256) {
        int bb = idx & 63, k = idx >> 6;
        fcol[k * 64 + bb] = feats_t[bb * D + d_lo + k];
    }
    // Wp[k][tn][j]: j=2*uu+p; p=0 -> (w_i,w_f) at n=(0,1)*40+u; p=1 -> (w_c,w_o)
    for (int idx = tid; idx < KE * 80; idx += 256) {
        int k = idx / 80, j8 = idx - k * 80;
        int tn_ = j8 / 10, j = j8 - tn_ * 10;
        int uu = j >> 1, p = j & 1;
        int u = tn_ * 5 + uu;
        int n0 = (p ? 2 : 0) * 40 + u;
        int n1 = (p ? 3 : 1) * 40 + u;
        const float* src = (k < 3) ? (kern + grp * 800 + k * NZ)
                                   : (rkern + grp * 6400 + (k - 3) * NZ);
        Wp[idx] = pack2(src[n0], src[n1]);
    }
    __syncthreads();

    // ---- phase 0b: loss reduce (warp 0) + grads into gbuf (all) ----
    if (tid < 32) {
        float v = g_losspart[tid] + g_losspart[tid + 32]
                + g_losspart[tid + 64] + g_losspart[tid + 96];
#pragma unroll
        for (int off = 16; off > 0; off >>= 1)
            v += __shfl_xor_sync(0xffffffffu, v, off);
        if (tid == 0) {
            float L = v * (1.0f / 16384.0f);
            float a = fabsf(L);
            if (a > NEGEXPP) {
                scal[0] = logf(a) / PREP;
                scal[1] = (L > 0.f) ? 1.f : ((L < 0.f) ? -1.f : 0.f);
            } else {
                scal[0] = -1.f;
                scal[1] = EXPP * L;
            }
        }
    }
    {
        int cc = (start64 + tid) & 255;
        float acc0 = 0.f, acc1 = 0.f;
        int dk0 = ((start64 + tid) >> 8) - d_lo;
        int dk1 = dk0 + 1;
        int n1 = nc - 256;
#pragma unroll 8
        for (int bb = 0; bb < B; bb++) {
            float ev = g_e[bb * C + cc];
            acc0 = fmaf(fcol[dk0 * 64 + bb], ev, acc0);
            if (tid < n1) acc1 = fmaf(fcol[dk1 * 64 + bb], ev, acc1);
        }
        gbuf[tid] = acc0;
        if (tid < n1) gbuf[tid + 256] = acc1;
    }
    __syncthreads();

    // ---- phase 0c: effective bias (l0,l1 folded), gate-paired ----
    float l0 = scal[0], l1 = scal[1], bfv = scal[2], biv = scal[3];
    if (tid < 80) {
        int tn_ = tid / 10, j = tid - tn_ * 10;
        int uu = j >> 1, p = j & 1;
        int u = tn_ * 5 + uu;
        int n0 = (p ? 2 : 0) * 40 + u;
        int n1 = (p ? 3 : 1) * 40 + u;
        const float* kb = kern + grp * 800;
        float b0 = bias[grp * NZ + n0] + l0 * kb[3 * NZ + n0] + l1 * kb[4 * NZ + n0];
        float b1 = bias[grp * NZ + n1] + l0 * kb[3 * NZ + n1] + l1 * kb[4 * NZ + n1];
        bp[tid] = pack2(b0, b1);
    }

    int tm = tid & 31;            // coord pair (2tm, 2tm+1)
    int tn = tid >> 5;            // u-range tn*5..tn*5+4
    int u0 = tn * 5;
    const unsigned long long* wthr = Wp + tn * 10;
    const unsigned long long* bthr = bp + tn * 10;

    for (int it = 0; it < ntiles; it++) {
        int base = start64 + it * 64;
        int rel = it * 64;

        // ---- fill xs ----
        if (tid < 64) {
            int coord = base + tid;
            float pv = t0 ? params[coord] : g_p[coord];
            float gv = gbuf[rel + tid];
            float a = fabsf(gv);
            float g0, g1;
            if (a > NEGEXPP) {
                g0 = logf(a) / PREP;
                g1 = (gv > 0.f) ? 1.f : ((gv < 0.f) ? -1.f : 0.f);
            } else {
                g0 = -1.f;
                g1 = EXPP * gv;
            }
            xs[0 * XS_STR + tid] = pv;
            xs[1 * XS_STR + tid] = g0;
            xs[2 * XS_STR + tid] = g1;
        }
        if (t0) {
            for (int idx = tid; idx < 32 * U; idx += 256) {
                int u = idx >> 5, m2 = idx & 31;
                *(float2*)(xs + (3 + u) * XS_STR + 2 * m2) = make_float2(0.f, 0.f);
            }
        } else {
            for (int idx = tid; idx < 32 * U; idx += 256) {
                int u = idx >> 5, m2 = idx & 31;
                float2 hv = *(const float2*)(g_h + (size_t)u * P + base + 2 * m2);
                *(float2*)(xs + (3 + u) * XS_STR + 2 * m2) = hv;
            }
        }
        __syncthreads();

        // ---- GEMM: gate-paired FFMA2.  acc[m*10+2uu+p] ----
        unsigned long long acc[20];
#pragma unroll
        for (int j = 0; j < 10; j++) {
            unsigned long long bv = bthr[j];
            acc[j] = bv; acc[10 + j] = bv;
        }

#pragma unroll 2
        for (int k = 0; k < KE; k++) {
            float2 xv = *(const float2*)(xs + k * XS_STR + 2 * tm);
            unsigned long long s0 = pack2(xv.x, xv.x);
            unsigned long long s1 = pack2(xv.y, xv.y);
            const unsigned long long* wp = wthr + k * 80;
            ulonglong2 w01 = *(const ulonglong2*)(wp);
            ulonglong2 w23 = *(const ulonglong2*)(wp + 2);
            ulonglong2 w45 = *(const ulonglong2*)(wp + 4);
            ulonglong2 w67 = *(const ulonglong2*)(wp + 6);
            ulonglong2 w89 = *(const ulonglong2*)(wp + 8);
            FMA2(acc[0], s0, w01.x);  FMA2(acc[10], s1, w01.x);
            FMA2(acc[1], s0, w01.y);  FMA2(acc[11], s1, w01.y);
            FMA2(acc[2], s0, w23.x);  FMA2(acc[12], s1, w23.x);
            FMA2(acc[3], s0, w23.y);  FMA2(acc[13], s1, w23.y);
            FMA2(acc[4], s0, w45.x);  FMA2(acc[14], s1, w45.x);
            FMA2(acc[5], s0, w45.y);  FMA2(acc[15], s1, w45.y);
            FMA2(acc[6], s0, w67.x);  FMA2(acc[16], s1, w67.x);
            FMA2(acc[7], s0, w67.y);  FMA2(acc[17], s1, w67.y);
            FMA2(acc[8], s0, w89.x);  FMA2(acc[18], s1, w89.x);
            FMA2(acc[9], s0, w89.y);  FMA2(acc[19], s1, w89.y);
        }

        // ---- gates + cell update + f/i partials (registers) ----
        float pf0 = 0.f, pf1 = 0.f, pi0 = 0.f, pi1 = 0.f;
#pragma unroll
        for (int uu = 0; uu < 5; uu++) {
            int u = u0 + uu;
            float2 if0 = u2f(acc[2 * uu]);        // m0: (z_i, z_f)
            float2 co0 = u2f(acc[2 * uu + 1]);    // m0: (z_c, z_o)
            float2 if1 = u2f(acc[10 + 2 * uu]);   // m1
            float2 co1 = u2f(acc[10 + 2 * uu + 1]);
            size_t off = (size_t)u * P + base + 2 * tm;
            float2 cp = t0 ? make_float2(0.f, 0.f)
                           : *(const float2*)(g_c + off);
            float cn0 = fmaf(hsig(if0.y), cp.x, hsig(if0.x) * tanh_fma(co0.x));
            float cn1 = fmaf(hsig(if1.y), cp.y, hsig(if1.x) * tanh_fma(co1.x));
            float hn0 = hsig(co0.y) * tanh_fma(cn0);
            float hn1 = hsig(co1.y) * tanh_fma(cn1);
            *(float2*)(g_c + off) = make_float2(cn0, cn1);
            *(float2*)(g_h + off) = make_float2(hn0, hn1);
            float wf = Wf_s[u], wi = Wi_s[u];
            pf0 = fmaf(hn0, wf, pf0);
            pf1 = fmaf(hn1, wf, pf1);
            pi0 = fmaf(hn0, wi, pi0);
            pi1 = fmaf(hn1, wi, pi1);
        }
        prF[tn * 32 + tm] = make_float2(pf0, pf1);
        prI[tn * 32 + tm] = make_float2(pi0, pi1);
        __syncthreads();

        // ---- reduce partials + param update (tid < 64) ----
        if (tid < 64) {
            int m = tid;
            int coord = base + m;
            int half_ = m & 1, mp = m >> 1;
            float pf = 0.f, pi = 0.f;
#pragma unroll
            for (int w = 0; w < 8; w++) {
                float2 vf = prF[w * 32 + mp];
                float2 vi = prI[w * 32 + mp];
                pf += half_ ? vf.y : vf.x;
                pi += half_ ? vi.y : vi.x;
            }
            float fprev = t0 ? 0.f : g_f[coord];
            float iprev = t0 ? 0.f : g_i[coord];
            float fnew = fmaxf(fmaf(fprev, Wf_s[40], pf) + bfv, 0.f);
            float inew = fmaxf(fmaf(iprev, Wi_s[40], pi) + biv, 0.f);
            float pold = xs[0 * XS_STR + m];
            float gv = gbuf[rel + m];
            float pnew = fnew * pold - inew * gv;
            g_f[coord] = fnew;
            g_i[coord] = inew;
            if (last) outp[coord] = pnew;
            else      g_p[coord] = pnew;
        }
        __syncthreads();   // before next tile reuses xs/prF/prI
    }
}

// ---------------------------------------------------------------------------
extern "C" void kernel_launch(void* const* d_in, const int* in_sizes, int n_in,
                              void* d_out, int out_size)
{
    const float* feats  = (const float*)d_in[0];
    const float* labels = (const float*)d_in[1];
    const float* params = (const float*)d_in[2];
    const float* kern   = (const float*)d_in[3];
    const float* rkern  = (const float*)d_in[4];
    const float* bias   = (const float*)d_in[5];
    const float* Wf     = (const float*)d_in[6];
    const float* bf     = (const float*)d_in[7];
    const float* Wi     = (const float*)d_in[8];
    const float* bi     = (const float*)d_in[9];
    float* out = (float*)d_out;

    cudaFuncSetAttribute(stepC, cudaFuncAttributeMaxDynamicSharedMemorySize,
                         SMEM_C_BYTES);

    for (int t = 0; t < T; t++) {
        const float* ft = feats  + (size_t)t * B * D;
        const float* lt = labels + (size_t)t * B * C;
        int t0 = (t == 0) ? 1 : 0;
        int last = (t == T - 1) ? 1 : 0;
        stepA<<<128, 256>>>(ft, lt, params, t0);
        stepC<<<NBLK_C, 256, SMEM_C_BYTES>>>(ft, kern, rkern, bias,
                                             Wf, bf, Wi, bi,
                                             params, out, t0, last);
    }
}